// round 4
// baseline (speedup 1.0000x reference)
#include <cuda_runtime.h>
#include <cstdint>

// ---------------------------------------------------------------------------
// NetVLAD on GB300 — round 1: compute-bound fp32x2 restructure
// N=32, C=1024, S=784 (pad 896), D=128, K=64, OUT=1024
// ---------------------------------------------------------------------------

#define SP 896   // padded spatial extent; pad columns forced to zero

__device__ float g_WpoolT[1024 * 128];        // [c][d]
__device__ float g_xf   [32 * 128 * SP];      // [n][d][s]
__device__ float g_sa   [32 * 64  * SP];      // [n][k][s]
__device__ float g_sasum[32 * 64];
__device__ float g_vlad [32 * 8192];
__device__ float g_proj [32 * 1024];

#define FMA2(acc, a, b) \
    asm("fma.rn.f32x2 %0, %1, %2, %0;" : "+l"(acc) : "l"(a), "l"(b))
#define DUP2(d, s) \
    asm("mov.b64 %0, {%1, %1};" : "=l"(d) : "f"(s))
#define UNPK(lo, hi, s) \
    asm("mov.b64 {%0, %1}, %2;" : "=f"(lo), "=f"(hi) : "l"(s))

// ---------------------------------------------------------------------------
__global__ void kT(const float* __restrict__ Wpool) {
    int idx = blockIdx.x * 256 + threadIdx.x;
    if (idx < 128 * 1024) {
        int c = idx >> 7, d = idx & 127;
        g_WpoolT[idx] = Wpool[d * 1024 + c];
    }
}

__global__ void kZ() {
    int idx = blockIdx.x * 256 + threadIdx.x;
    if (idx < 32 * 64)   g_sasum[idx] = 0.f;
    if (idx < 32 * 1024) g_proj[idx]  = 0.f;
}

// ---------------------------------------------------------------------------
// kA: pool GEMM (128d x 128s per block) + bias + col L2 norm + logits + softmax
// grid (7 s-tiles, 32 n), 256 threads, dyn smem 111616 B
// float offsets:
//   region A [0, 8704): Ws[16][132] (0..2112) + Xs[16][132] (2112..4224)
//                        later reused as WconvT[128][68]  (0..8704)
//   [8704, 25600)  xfS[128][132]
//   [25600, 27776) part[128][17]  (also reused as [64][34])
//   [27776, 27904) colbuf[128]    (cinv / softmax max / softmax 1/sum)
// ---------------------------------------------------------------------------
__global__ void __launch_bounds__(256) kA(const float* __restrict__ x,
                                          const float* __restrict__ bpool,
                                          const float* __restrict__ Wconv,
                                          const float* __restrict__ bconv) {
    extern __shared__ float sm[];
    const int OFF_WS = 0, OFF_XS = 2112, OFF_WCT = 0;
    const int OFF_XF = 8704, OFF_PART = 25600, OFF_COL = 27776;

    const int tid = threadIdx.x;
    const int n = blockIdx.y;
    const int s0 = blockIdx.x * 128;
    const int gs = tid >> 4;     // 0..15 -> s base gs*8
    const int gd = tid & 15;     // 0..15 -> d base gd*8

    unsigned long long acc[4][8];
#pragma unroll
    for (int p = 0; p < 4; p++)
#pragma unroll
        for (int j = 0; j < 8; j++) acc[p][j] = 0ull;

    const int stc = tid >> 4;          // 0..15 : cc row for staging
    const int st8 = (tid & 15) * 8;    // 0..120: col base for staging

    const float* xn = x + (size_t)n * 1024 * 784;
    const bool fullv = (s0 + 128) <= 784;

    for (int c0 = 0; c0 < 1024; c0 += 16) {
        __syncthreads();
        // W tile [cc][d]
        {
            const float* wr = &g_WpoolT[(c0 + stc) * 128 + st8];
            float4 w0 = *(const float4*)&wr[0];
            float4 w1 = *(const float4*)&wr[4];
            *(float4*)&sm[OFF_WS + stc * 132 + st8]     = w0;
            *(float4*)&sm[OFF_WS + stc * 132 + st8 + 4] = w1;
        }
        // X tile [cc][s]
        {
            const float* xr = &xn[(c0 + stc) * 784];
            float4 x0, x1;
            if (fullv) {
                x0 = *(const float4*)&xr[s0 + st8];
                x1 = *(const float4*)&xr[s0 + st8 + 4];
            } else {
                float t[8];
#pragma unroll
                for (int u = 0; u < 8; u++) {
                    int sc = s0 + st8 + u;
                    t[u] = (sc < 784) ? xr[sc] : 0.f;
                }
                x0.x = t[0]; x0.y = t[1]; x0.z = t[2]; x0.w = t[3];
                x1.x = t[4]; x1.y = t[5]; x1.z = t[6]; x1.w = t[7];
            }
            *(float4*)&sm[OFF_XS + stc * 132 + st8]     = x0;
            *(float4*)&sm[OFF_XS + stc * 132 + st8 + 4] = x1;
        }
        __syncthreads();
#pragma unroll
        for (int cc = 0; cc < 16; cc++) {
            ulonglong2 w0 = *(const ulonglong2*)&sm[OFF_WS + cc * 132 + gd * 8];
            ulonglong2 w1 = *(const ulonglong2*)&sm[OFF_WS + cc * 132 + gd * 8 + 4];
            float4 xl = *(const float4*)&sm[OFF_XS + cc * 132 + gs * 8];
            float4 xh = *(const float4*)&sm[OFF_XS + cc * 132 + gs * 8 + 4];
            unsigned long long xd[8];
            DUP2(xd[0], xl.x); DUP2(xd[1], xl.y); DUP2(xd[2], xl.z); DUP2(xd[3], xl.w);
            DUP2(xd[4], xh.x); DUP2(xd[5], xh.y); DUP2(xd[6], xh.z); DUP2(xd[7], xh.w);
#pragma unroll
            for (int j = 0; j < 8; j++) {
                FMA2(acc[0][j], w0.x, xd[j]);
                FMA2(acc[1][j], w0.y, xd[j]);
                FMA2(acc[2][j], w1.x, xd[j]);
                FMA2(acc[3][j], w1.y, xd[j]);
            }
        }
    }

    // ---- unpack + bias ----
    float pv[8][8];
#pragma unroll
    for (int p = 0; p < 4; p++)
#pragma unroll
        for (int j = 0; j < 8; j++)
            UNPK(pv[2 * p][j], pv[2 * p + 1][j], acc[p][j]);
#pragma unroll
    for (int i = 0; i < 8; i++) {
        float b = bpool[gd * 8 + i];
#pragma unroll
        for (int j = 0; j < 8; j++) pv[i][j] += b;
    }

    // ---- column L2 norm over d ----
#pragma unroll
    for (int j = 0; j < 8; j++) {
        float s = 0.f;
#pragma unroll
        for (int i = 0; i < 8; i++) s += pv[i][j] * pv[i][j];
        sm[OFF_PART + (gs * 8 + j) * 17 + gd] = s;
    }
    __syncthreads();
    if (tid < 128) {
        float s = 0.f;
#pragma unroll
        for (int t = 0; t < 16; t++) s += sm[OFF_PART + tid * 17 + t];
        sm[OFF_COL + tid] = 1.f / fmaxf(sqrtf(s), 1e-12f);
    }
    __syncthreads();

    // ---- normalize (zero pad cols), write xf (gmem) + xfS (smem) ----
#pragma unroll
    for (int j = 0; j < 8; j++) {
        bool v = (s0 + gs * 8 + j) < 784;
        float m = v ? sm[OFF_COL + gs * 8 + j] : 0.f;
#pragma unroll
        for (int i = 0; i < 8; i++) pv[i][j] *= m;
    }
    float* xfn = g_xf + (size_t)n * 128 * SP;
#pragma unroll
    for (int i = 0; i < 8; i++) {
        int d = gd * 8 + i;
        float4 o0, o1;
        o0.x = pv[i][0]; o0.y = pv[i][1]; o0.z = pv[i][2]; o0.w = pv[i][3];
        o1.x = pv[i][4]; o1.y = pv[i][5]; o1.z = pv[i][6]; o1.w = pv[i][7];
        *(float4*)&xfn[(size_t)d * SP + s0 + gs * 8]     = o0;
        *(float4*)&xfn[(size_t)d * SP + s0 + gs * 8 + 4] = o1;
        *(float4*)&sm[OFF_XF + d * 132 + gs * 8]     = o0;
        *(float4*)&sm[OFF_XF + d * 132 + gs * 8 + 4] = o1;
    }

    // ---- stage WconvT [d][k] (overwrites Ws/Xs region) ----
    {
        int kr = tid & 63, dg = tid >> 6;   // cols dg*32..+31
#pragma unroll
        for (int u = 0; u < 8; u++) {
            float4 w = *(const float4*)&Wconv[kr * 128 + dg * 32 + u * 4];
            sm[OFF_WCT + (dg * 32 + u * 4 + 0) * 68 + kr] = w.x;
            sm[OFF_WCT + (dg * 32 + u * 4 + 1) * 68 + kr] = w.y;
            sm[OFF_WCT + (dg * 32 + u * 4 + 2) * 68 + kr] = w.z;
            sm[OFF_WCT + (dg * 32 + u * 4 + 3) * 68 + kr] = w.w;
        }
    }
    __syncthreads();

    // ---- logits: a2[kpair][4 s], FMA2 over k-pairs ----
    const int kg = tid & 7;      // k base kg*8
    const int sc = tid >> 3;     // 0..31, s base sc*4
    unsigned long long a2[4][4];
#pragma unroll
    for (int p = 0; p < 4; p++)
#pragma unroll
        for (int j = 0; j < 4; j++) a2[p][j] = 0ull;
    for (int d = 0; d < 128; d++) {
        ulonglong2 w0 = *(const ulonglong2*)&sm[OFF_WCT + d * 68 + kg * 8];
        ulonglong2 w1 = *(const ulonglong2*)&sm[OFF_WCT + d * 68 + kg * 8 + 4];
        float4 xv = *(const float4*)&sm[OFF_XF + d * 132 + sc * 4];
        unsigned long long xd[4];
        DUP2(xd[0], xv.x); DUP2(xd[1], xv.y); DUP2(xd[2], xv.z); DUP2(xd[3], xv.w);
#pragma unroll
        for (int j = 0; j < 4; j++) {
            FMA2(a2[0][j], w0.x, xd[j]);
            FMA2(a2[1][j], w0.y, xd[j]);
            FMA2(a2[2][j], w1.x, xd[j]);
            FMA2(a2[3][j], w1.y, xd[j]);
        }
    }
    float l[8][4];
#pragma unroll
    for (int p = 0; p < 4; p++)
#pragma unroll
        for (int j = 0; j < 4; j++)
            UNPK(l[2 * p][j], l[2 * p + 1][j], a2[p][j]);
#pragma unroll
    for (int i = 0; i < 8; i++) {
        float b = bconv[kg * 8 + i];
#pragma unroll
        for (int j = 0; j < 4; j++) l[i][j] += b;
    }

    // ---- softmax over K=64 per column ----
#pragma unroll
    for (int j = 0; j < 4; j++) {
        float m = l[0][j];
#pragma unroll
        for (int i = 1; i < 8; i++) m = fmaxf(m, l[i][j]);
        sm[OFF_PART + (sc * 4 + j) * 17 + kg] = m;
    }
    __syncthreads();
    if (tid < 128) {
        float m = sm[OFF_PART + tid * 17];
#pragma unroll
        for (int t = 1; t < 8; t++) m = fmaxf(m, sm[OFF_PART + tid * 17 + t]);
        sm[OFF_COL + tid] = m;
    }
    __syncthreads();
    float e[8][4];
#pragma unroll
    for (int j = 0; j < 4; j++) {
        float M = sm[OFF_COL + sc * 4 + j];
        float ssum = 0.f;
#pragma unroll
        for (int i = 0; i < 8; i++) { e[i][j] = __expf(l[i][j] - M); ssum += e[i][j]; }
        sm[OFF_PART + (sc * 4 + j) * 17 + kg] = ssum;
    }
    __syncthreads();
    if (tid < 128) {
        float t = 0.f;
#pragma unroll
        for (int q = 0; q < 8; q++) t += sm[OFF_PART + tid * 17 + q];
        sm[OFF_COL + tid] = 1.f / t;
    }
    __syncthreads();

    // ---- write sa (zero pad cols) + sasum partials ----
    float ps[8];
#pragma unroll
    for (int i = 0; i < 8; i++) ps[i] = 0.f;
    float* san = g_sa + (size_t)n * 64 * SP;
#pragma unroll
    for (int j = 0; j < 4; j++) {
        int sl = sc * 4 + j;
        bool v = (s0 + sl) < 784;
        float r = v ? sm[OFF_COL + sl] : 0.f;
#pragma unroll
        for (int i = 0; i < 8; i++) {
            float val = e[i][j] * r;
            san[(size_t)(kg * 8 + i) * SP + s0 + sl] = val;
            ps[i] += val;
        }
    }
    __syncthreads();   // part buffer reuse as [64][34]
#pragma unroll
    for (int i = 0; i < 8; i++)
        sm[OFF_PART + (kg * 8 + i) * 34 + sc] = ps[i];
    __syncthreads();
    if (tid < 64) {
        float s = 0.f;
#pragma unroll
        for (int c = 0; c < 32; c++) s += sm[OFF_PART + tid * 34 + c];
        atomicAdd(&g_sasum[n * 64 + tid], s);
    }
}

// ---------------------------------------------------------------------------
// kB: vlad = sa @ xf^T - centroids * sasum, fused intra-norm over K
// grid (4 d-tiles of 32, 32 n), 256 threads
// ---------------------------------------------------------------------------
__global__ void __launch_bounds__(256) kB(const float* __restrict__ centroids) {
    __shared__ float saT[32 * 68];   // [ss][k]
    __shared__ float xfT[32 * 36];   // [ss][dloc]
    __shared__ float red[32 * 17];
    __shared__ float dinv[32];

    const int tid = threadIdx.x;
    const int dt = blockIdx.x;
    const int n = blockIdx.y;
    const int tk = tid >> 4;     // k base tk*4
    const int td = tid & 15;     // d pair base td*2

    unsigned long long acc[4];
#pragma unroll
    for (int q = 0; q < 4; q++) acc[q] = 0ull;

    const int skr = tid & 63, scg = tid >> 6;   // sa stage
    const int xdr = tid & 31, xcg = tid >> 5;   // xf stage
    const float* san = g_sa + (size_t)n * 64 * SP;
    const float* xfn = g_xf + (size_t)n * 128 * SP + (size_t)dt * 32 * SP;

    for (int sb = 0; sb < SP; sb += 32) {
        __syncthreads();
        {
            float4 a = *(const float4*)&san[(size_t)skr * SP + sb + scg * 8];
            float4 b = *(const float4*)&san[(size_t)skr * SP + sb + scg * 8 + 4];
            saT[(scg * 8 + 0) * 68 + skr] = a.x;
            saT[(scg * 8 + 1) * 68 + skr] = a.y;
            saT[(scg * 8 + 2) * 68 + skr] = a.z;
            saT[(scg * 8 + 3) * 68 + skr] = a.w;
            saT[(scg * 8 + 4) * 68 + skr] = b.x;
            saT[(scg * 8 + 5) * 68 + skr] = b.y;
            saT[(scg * 8 + 6) * 68 + skr] = b.z;
            saT[(scg * 8 + 7) * 68 + skr] = b.w;
            float4 c = *(const float4*)&xfn[(size_t)xdr * SP + sb + xcg * 4];
            xfT[(xcg * 4 + 0) * 36 + xdr] = c.x;
            xfT[(xcg * 4 + 1) * 36 + xdr] = c.y;
            xfT[(xcg * 4 + 2) * 36 + xdr] = c.z;
            xfT[(xcg * 4 + 3) * 36 + xdr] = c.w;
        }
        __syncthreads();
#pragma unroll
        for (int ss = 0; ss < 32; ss++) {
            float4 sv = *(const float4*)&saT[ss * 68 + tk * 4];
            unsigned long long xp = *(const unsigned long long*)&xfT[ss * 36 + td * 2];
            unsigned long long d0, d1, d2, d3;
            DUP2(d0, sv.x); DUP2(d1, sv.y); DUP2(d2, sv.z); DUP2(d3, sv.w);
            FMA2(acc[0], d0, xp);
            FMA2(acc[1], d1, xp);
            FMA2(acc[2], d2, xp);
            FMA2(acc[3], d3, xp);
        }
    }

    float v[4][2];
#pragma unroll
    for (int q = 0; q < 4; q++) {
        UNPK(v[q][0], v[q][1], acc[q]);
        float sq = g_sasum[n * 64 + tk * 4 + q];
#pragma unroll
        for (int r = 0; r < 2; r++) {
            int dg = dt * 32 + td * 2 + r;
            v[q][r] -= centroids[(tk * 4 + q) * 128 + dg] * sq;
        }
    }
#pragma unroll
    for (int r = 0; r < 2; r++) {
        float s = 0.f;
#pragma unroll
        for (int q = 0; q < 4; q++) s += v[q][r] * v[q][r];
        red[(td * 2 + r) * 17 + tk] = s;
    }
    __syncthreads();
    if (tid < 32) {
        float s = 0.f;
#pragma unroll
        for (int t = 0; t < 16; t++) s += red[tid * 17 + t];
        dinv[tid] = 1.f / fmaxf(sqrtf(s), 1e-12f);
    }
    __syncthreads();
    float* vn = g_vlad + (size_t)n * 8192;
#pragma unroll
    for (int q = 0; q < 4; q++)
#pragma unroll
        for (int r = 0; r < 2; r++) {
            int dg = dt * 32 + td * 2 + r;
            vn[(tk * 4 + q) * 128 + dg] = v[q][r] * dinv[td * 2 + r];
        }
}

// ---------------------------------------------------------------------------
// kC: proj += vlad @ Wproj^T.  grid (32 o-tiles of 32, 4 j-splits), 128 thr
// ---------------------------------------------------------------------------
__global__ void __launch_bounds__(128) kC(const float* __restrict__ Wproj) {
    __shared__ float wS[32 * 68];   // [o][j]
    __shared__ float vT[64 * 36];   // [j][n]

    const int tid = threadIdx.x;
    const int ob = blockIdx.x * 32;
    const int jb = blockIdx.y * 2048;
    const int to = tid >> 2;      // o local 0..31
    const int ng = tid & 3;       // n base ng*8

    unsigned long long acc[4];
#pragma unroll
    for (int q = 0; q < 4; q++) acc[q] = 0ull;

    const int sr = tid & 31, scg = tid >> 5;   // staging: row, col-group*16

    for (int jt = 0; jt < 2048; jt += 64) {
        __syncthreads();
        {
            const float* wr = &Wproj[(size_t)(ob + sr) * 8192 + jb + jt + scg * 16];
#pragma unroll
            for (int u = 0; u < 4; u++)
                *(float4*)&wS[sr * 68 + scg * 16 + u * 4] = *(const float4*)&wr[u * 4];
            const float* vr = &g_vlad[(size_t)sr * 8192 + jb + jt + scg * 16];
#pragma unroll
            for (int u = 0; u < 4; u++) {
                float4 v4 = *(const float4*)&vr[u * 4];
                vT[(scg * 16 + u * 4 + 0) * 36 + sr] = v4.x;
                vT[(scg * 16 + u * 4 + 1) * 36 + sr] = v4.y;
                vT[(scg * 16 + u * 4 + 2) * 36 + sr] = v4.z;
                vT[(scg * 16 + u * 4 + 3) * 36 + sr] = v4.w;
            }
        }
        __syncthreads();
#pragma unroll
        for (int j = 0; j < 64; j++) {
            float w = wS[to * 68 + j];
            ulonglong2 v0 = *(const ulonglong2*)&vT[j * 36 + ng * 8];
            ulonglong2 v1 = *(const ulonglong2*)&vT[j * 36 + ng * 8 + 4];
            unsigned long long wd;
            DUP2(wd, w);
            FMA2(acc[0], wd, v0.x);
            FMA2(acc[1], wd, v0.y);
            FMA2(acc[2], wd, v1.x);
            FMA2(acc[3], wd, v1.y);
        }
    }
#pragma unroll
    for (int q = 0; q < 4; q++) {
        float lo, hi;
        UNPK(lo, hi, acc[q]);
        atomicAdd(&g_proj[(ng * 8 + 2 * q) * 1024 + ob + to], lo);
        atomicAdd(&g_proj[(ng * 8 + 2 * q + 1) * 1024 + ob + to], hi);
    }
}

// ---------------------------------------------------------------------------
// kD: bias + final L2 norm -> output
// ---------------------------------------------------------------------------
__global__ void __launch_bounds__(256) kD(const float* __restrict__ bproj,
                                          float* __restrict__ out) {
    __shared__ float wr[8];
    __shared__ float inv_s;
    const int n = blockIdx.x, tid = threadIdx.x;
    float v[4]; float ps = 0.f;
#pragma unroll
    for (int r = 0; r < 4; r++) {
        int o = r * 256 + tid;
        v[r] = g_proj[n * 1024 + o] + bproj[o];
        ps += v[r] * v[r];
    }
#pragma unroll
    for (int off = 16; off; off >>= 1)
        ps += __shfl_xor_sync(0xffffffffu, ps, off);
    if ((tid & 31) == 0) wr[tid >> 5] = ps;
    __syncthreads();
    if (tid == 0) {
        float s = 0.f;
#pragma unroll
        for (int t = 0; t < 8; t++) s += wr[t];
        inv_s = 1.f / fmaxf(sqrtf(s), 1e-12f);
    }
    __syncthreads();
#pragma unroll
    for (int r = 0; r < 4; r++)
        out[n * 1024 + r * 256 + tid] = v[r] * inv_s;
}

// ---------------------------------------------------------------------------
extern "C" void kernel_launch(void* const* d_in, const int* in_sizes, int n_in,
                              void* d_out, int out_size) {
    const float* x         = (const float*)d_in[0];
    const float* Wpool     = (const float*)d_in[1];
    const float* bpool     = (const float*)d_in[2];
    const float* Wconv     = (const float*)d_in[3];
    const float* bconv     = (const float*)d_in[4];
    const float* centroids = (const float*)d_in[5];
    const float* Wproj     = (const float*)d_in[6];
    const float* bproj     = (const float*)d_in[7];
    float* out = (float*)d_out;

    cudaFuncSetAttribute(kA, cudaFuncAttributeMaxDynamicSharedMemorySize, 111616);

    kT<<<512, 256>>>(Wpool);
    kZ<<<128, 256>>>();
    dim3 gA(7, 32);
    kA<<<gA, 256, 111616>>>(x, bpool, Wconv, bconv);
    dim3 gB(4, 32);
    kB<<<gB, 256>>>(centroids);
    dim3 gC(32, 4);
    kC<<<gC, 128>>>(Wproj);
    kD<<<32, 256>>>(bproj, out);
}

// round 6
// speedup vs baseline: 1.8621x; 1.8621x over previous
#include <cuda_runtime.h>
#include <cuda_bf16.h>
#include <cstdint>

// ---------------------------------------------------------------------------
// NetVLAD GB300 round 5: mma.sync bf16-split pool GEMM (HMMA path) + fused
// vlad partial epilogue.  N=32, C=1024, D=128, K=64, S=784 (7 tiles), OUT=1024
// ---------------------------------------------------------------------------

__device__ __nv_bfloat16 g_wh[131072];    // Wpool hi [d][c]
__device__ __nv_bfloat16 g_wl[131072];    // Wpool lo [d][c]
__device__ float g_vladraw[32 * 8192];
__device__ float g_vlad  [32 * 8192];
__device__ float g_sasum [32 * 64];
__device__ float g_proj  [32 * 1024];

#define FMA2(acc, a, b) \
    asm("fma.rn.f32x2 %0, %1, %2, %0;" : "+l"(acc) : "l"(a), "l"(b))
#define DUP2(d, s) \
    asm("mov.b64 %0, {%1, %1};" : "=l"(d) : "f"(s))
#define UNPK(lo, hi, s) \
    asm("mov.b64 {%0, %1}, %2;" : "=f"(lo), "=f"(hi) : "l"(s))

__device__ __forceinline__ uint32_t smem_u32(const void* p) {
    uint32_t a;
    asm("{ .reg .u64 t; cvta.to.shared.u64 t, %1; cvt.u32.u64 %0, t; }"
        : "=r"(a) : "l"(p));
    return a;
}

__device__ __forceinline__ void ldsm(unsigned* r, uint32_t a) {
    asm volatile("ldmatrix.sync.aligned.m8n8.x4.shared.b16 {%0,%1,%2,%3}, [%4];"
        : "=r"(r[0]), "=r"(r[1]), "=r"(r[2]), "=r"(r[3]) : "r"(a));
}
__device__ __forceinline__ void ldsmt(unsigned* r, uint32_t a) {
    asm volatile("ldmatrix.sync.aligned.m8n8.x4.trans.shared.b16 {%0,%1,%2,%3}, [%4];"
        : "=r"(r[0]), "=r"(r[1]), "=r"(r[2]), "=r"(r[3]) : "r"(a));
}
__device__ __forceinline__ void mma_bf16(float* c, const unsigned* a, const unsigned* b) {
    asm volatile(
        "mma.sync.aligned.m16n8k16.row.col.f32.bf16.bf16.f32 "
        "{%0,%1,%2,%3}, {%4,%5,%6,%7}, {%8,%9}, {%0,%1,%2,%3};"
        : "+f"(c[0]), "+f"(c[1]), "+f"(c[2]), "+f"(c[3])
        : "r"(a[0]), "r"(a[1]), "r"(a[2]), "r"(a[3]), "r"(b[0]), "r"(b[1]));
}

static __device__ __forceinline__ uint32_t packbf2(float a, float b) {
    __nv_bfloat162 t;
    t.x = __float2bfloat16(a);
    t.y = __float2bfloat16(b);
    return *(uint32_t*)&t;
}

// ---------------------------------------------------------------------------
// kW: split Wpool (row-major [d][c]) into bf16 hi/lo planes
// ---------------------------------------------------------------------------
__global__ void kW(const float* __restrict__ Wpool) {
    int idx = blockIdx.x * 256 + threadIdx.x;
    if (idx >= 131072) return;
    float w = Wpool[idx];
    __nv_bfloat16 h = __float2bfloat16(w);
    g_wh[idx] = h;
    g_wl[idx] = __float2bfloat16(w - __bfloat162float(h));
}

__global__ void kZ() {
    int idx = blockIdx.x * 256 + threadIdx.x;
    if (idx < 262144) g_vladraw[idx] = 0.f;
    if (idx < 2048)   g_sasum[idx] = 0.f;
    if (idx < 32768)  g_proj[idx] = 0.f;
}

// ---------------------------------------------------------------------------
// kA: HMMA pool GEMM + bias + col L2 norm + logits + softmax + vlad partial
// grid (7 s-tiles, 32 n), 256 threads, dyn smem 180224 B
// phase1 byte layout:
//   WH @1024  [128 d][72 bf16]   (144 B rows)  18432 B
//   WL @19456 same                             18432 B
//   XH @37888 [64 c][136 bf16]   (272 B rows)  17408 B
//   XL @55296 same                             17408 B
// phase2 float offsets: xfA@256 [128][132] (d,s), xfB@17152 [128][132] (s,d),
//   EP2@34048 (WconvT[128][68] then saT[128][68]), EP3@42752 [64..128][..],
//   EP4@44928 [128]
// ---------------------------------------------------------------------------
__global__ void __launch_bounds__(256) kA(const float* __restrict__ x,
                                          const float* __restrict__ bpool,
                                          const float* __restrict__ Wconv,
                                          const float* __restrict__ bconv) {
    extern __shared__ char smc[];
    float* smf = (float*)smc;
    const uint32_t sb = smem_u32(smc);

    const int tid = threadIdx.x, lane = tid & 31, wid = tid >> 5;
    const int n = blockIdx.y;
    const int s0 = blockIdx.x * 128;
    const bool fullv = (blockIdx.x < 6);

    const int WHo = 1024, WLo = 19456, XHo = 37888, XLo = 55296;

    const float* xn = x + (size_t)n * 1024 * 784;
    const int c2 = tid >> 3, sg = (tid & 7) * 16;     // X staging
    const int wrow = tid >> 1, wcol = (tid & 1) * 32; // W staging

    float acc[2][8][4];
#pragma unroll
    for (int mt = 0; mt < 2; mt++)
#pragma unroll
        for (int nf = 0; nf < 8; nf++)
#pragma unroll
            for (int u = 0; u < 4; u++) acc[mt][nf][u] = 0.f;

    float xr0[16], xr1[16];
    uint4 wreg[8];

#define LOADX(q) do { \
    const float* p0 = xn + (size_t)((q) * 64 + 2 * c2) * 784 + s0 + sg; \
    const float* p1 = p0 + 784; \
    if (fullv) { \
        _Pragma("unroll") \
        for (int u = 0; u < 4; u++) { \
            float4 a = ((const float4*)p0)[u]; \
            float4 b = ((const float4*)p1)[u]; \
            xr0[u*4] = a.x; xr0[u*4+1] = a.y; xr0[u*4+2] = a.z; xr0[u*4+3] = a.w; \
            xr1[u*4] = b.x; xr1[u*4+1] = b.y; xr1[u*4+2] = b.z; xr1[u*4+3] = b.w; \
        } \
    } else { \
        _Pragma("unroll") \
        for (int i = 0; i < 16; i++) { \
            bool v = (s0 + sg + i) < 784; \
            xr0[i] = v ? p0[i] : 0.f; \
            xr1[i] = v ? p1[i] : 0.f; \
        } \
    } } while (0)

#define LOADW(q) do { \
    const uint4* ph = (const uint4*)(g_wh + (size_t)wrow * 1024 + (q) * 64 + wcol); \
    const uint4* pl = (const uint4*)(g_wl + (size_t)wrow * 1024 + (q) * 64 + wcol); \
    _Pragma("unroll") \
    for (int u = 0; u < 4; u++) { wreg[u] = ph[u]; wreg[4 + u] = pl[u]; } \
    } while (0)

    LOADX(0);
    LOADW(0);

    const int wd = wid & 3, ws = wid >> 2;
    const int md0 = wd * 32, ns0 = ws * 64;
    const int mat = lane >> 3, rr = lane & 7;
    const uint32_t aH = sb + WHo + (uint32_t)(md0 + ((mat & 1) << 3) + rr) * 144
                        + ((uint32_t)(mat >> 1) << 4);
    const uint32_t aL = aH + (WLo - WHo);
    const uint32_t bHb = sb + XHo + (uint32_t)(((mat & 1) << 3) + rr) * 272
                         + (uint32_t)(ns0 + ((mat >> 1) << 3)) * 2;
    const uint32_t bLb = bHb + (XLo - XHo);

    for (int q = 0; q < 16; q++) {
        // store W
        {
            char* dh = smc + WHo + wrow * 144 + wcol * 2;
            char* dl = smc + WLo + wrow * 144 + wcol * 2;
#pragma unroll
            for (int u = 0; u < 4; u++) {
                ((uint4*)dh)[u] = wreg[u];
                ((uint4*)dl)[u] = wreg[4 + u];
            }
        }
        // store X (convert to bf16 hi/lo pairs)
        {
            char* xh0 = smc + XHo + (2 * c2) * 272 + sg * 2;
            char* xl0 = smc + XLo + (2 * c2) * 272 + sg * 2;
#pragma unroll
            for (int i = 0; i < 8; i++) {
                float v0 = xr0[2 * i], v1 = xr0[2 * i + 1];
                __nv_bfloat16 h0 = __float2bfloat16(v0);
                __nv_bfloat16 h1 = __float2bfloat16(v1);
                uint32_t hp;
                { __nv_bfloat162 t; t.x = h0; t.y = h1; hp = *(uint32_t*)&t; }
                *(uint32_t*)(xh0 + i * 4) = hp;
                *(uint32_t*)(xl0 + i * 4) =
                    packbf2(v0 - __bfloat162float(h0), v1 - __bfloat162float(h1));
                float w0 = xr1[2 * i], w1 = xr1[2 * i + 1];
                __nv_bfloat16 g0 = __float2bfloat16(w0);
                __nv_bfloat16 g1 = __float2bfloat16(w1);
                uint32_t gp;
                { __nv_bfloat162 t; t.x = g0; t.y = g1; gp = *(uint32_t*)&t; }
                *(uint32_t*)(xh0 + 272 + i * 4) = gp;
                *(uint32_t*)(xl0 + 272 + i * 4) =
                    packbf2(w0 - __bfloat162float(g0), w1 - __bfloat162float(g1));
            }
        }
        __syncthreads();
        if (q < 15) { LOADX(q + 1); LOADW(q + 1); }

        // mma on this chunk (k = 64, 4 k-steps)
#pragma unroll
        for (int ks = 0; ks < 4; ks++) {
            unsigned ah[2][4], al[2][4];
            ldsm(ah[0], aH + ks * 32);
            ldsm(ah[1], aH + ks * 32 + 2304);
            ldsm(al[0], aL + ks * 32);
            ldsm(al[1], aL + ks * 32 + 2304);
            unsigned bh[4][4], bl[4][4];
#pragma unroll
            for (int nt = 0; nt < 4; nt++) {
                ldsmt(bh[nt], bHb + ks * 4352 + nt * 32);
                ldsmt(bl[nt], bLb + ks * 4352 + nt * 32);
            }
#pragma unroll
            for (int mt = 0; mt < 2; mt++)
#pragma unroll
                for (int nf = 0; nf < 8; nf++) {
                    const unsigned* bhf = &bh[nf >> 1][(nf & 1) * 2];
                    const unsigned* blf = &bl[nf >> 1][(nf & 1) * 2];
                    mma_bf16(acc[mt][nf], ah[mt], bhf);
                    mma_bf16(acc[mt][nf], al[mt], bhf);
                    mma_bf16(acc[mt][nf], ah[mt], blf);
                }
        }
        __syncthreads();
    }
#undef LOADX
#undef LOADW

    // ---- acc -> xfA[d][s] (+bias) ----
    {
        const int r0w = lane >> 2, cq = (lane & 3) * 2;
#pragma unroll
        for (int mt = 0; mt < 2; mt++) {
            int d = md0 + mt * 16 + r0w;
            float b0 = __ldg(&bpool[d]);
            float b8 = __ldg(&bpool[d + 8]);
#pragma unroll
            for (int nf = 0; nf < 8; nf++) {
                int s = ns0 + nf * 8 + cq;
                smf[256 + d * 132 + s]             = acc[mt][nf][0] + b0;
                smf[256 + d * 132 + s + 1]         = acc[mt][nf][1] + b0;
                smf[256 + (d + 8) * 132 + s]       = acc[mt][nf][2] + b8;
                smf[256 + (d + 8) * 132 + s + 1]   = acc[mt][nf][3] + b8;
            }
        }
    }
    __syncthreads();

    const int half = tid >> 7;
    const int row = tid & 127;

    // ---- column L2 norm over d (invalid s -> factor 0) ----
    if (tid < 128) {
        float s = 0.f;
#pragma unroll 8
        for (int d = 0; d < 128; d++) {
            float v = smf[256 + d * 132 + tid];
            s += v * v;
        }
        smf[44928 + tid] = ((s0 + tid) < 784) ? 1.f / fmaxf(sqrtf(s), 1e-12f) : 0.f;
    }
    __syncthreads();

    // ---- normalize: update xfA, build xfB[s][d] ----
#pragma unroll
    for (int g = 0; g < 16; g++) {
        int s4 = half * 64 + g * 4;
        float4 v = *(const float4*)&smf[256 + row * 132 + s4];
        float4 m = *(const float4*)&smf[44928 + s4];
        v.x *= m.x; v.y *= m.y; v.z *= m.z; v.w *= m.w;
        *(float4*)&smf[256 + row * 132 + s4] = v;
        smf[17152 + (s4 + 0) * 132 + row] = v.x;
        smf[17152 + (s4 + 1) * 132 + row] = v.y;
        smf[17152 + (s4 + 2) * 132 + row] = v.z;
        smf[17152 + (s4 + 3) * 132 + row] = v.w;
    }

    // ---- stage WconvT[d][k] at EP2 ----
    {
        int kr = tid & 63, dq = tid >> 6;
#pragma unroll
        for (int u = 0; u < 8; u++) {
            float4 w = *(const float4*)&Wconv[kr * 128 + dq * 32 + u * 4];
            smf[34048 + (dq * 32 + u * 4 + 0) * 68 + kr] = w.x;
            smf[34048 + (dq * 32 + u * 4 + 1) * 68 + kr] = w.y;
            smf[34048 + (dq * 32 + u * 4 + 2) * 68 + kr] = w.z;
            smf[34048 + (dq * 32 + u * 4 + 3) * 68 + kr] = w.w;
        }
    }
    __syncthreads();

    // ---- logits: kg -> 8 k, sc -> 4 s ----
    const int kg = tid & 7;
    const int sc = tid >> 3;
    unsigned long long a2[4][4];
#pragma unroll
    for (int p = 0; p < 4; p++)
#pragma unroll
        for (int j = 0; j < 4; j++) a2[p][j] = 0ull;
    for (int d = 0; d < 128; d++) {
        ulonglong2 w0 = *(const ulonglong2*)&smf[34048 + d * 68 + kg * 8];
        ulonglong2 w1 = *(const ulonglong2*)&smf[34048 + d * 68 + kg * 8 + 4];
        float4 xv = *(const float4*)&smf[256 + d * 132 + sc * 4];
        unsigned long long xd[4];
        DUP2(xd[0], xv.x); DUP2(xd[1], xv.y); DUP2(xd[2], xv.z); DUP2(xd[3], xv.w);
#pragma unroll
        for (int j = 0; j < 4; j++) {
            FMA2(a2[0][j], w0.x, xd[j]);
            FMA2(a2[1][j], w0.y, xd[j]);
            FMA2(a2[2][j], w1.x, xd[j]);
            FMA2(a2[3][j], w1.y, xd[j]);
        }
    }
    float l[8][4];
#pragma unroll
    for (int p = 0; p < 4; p++)
#pragma unroll
        for (int j = 0; j < 4; j++)
            UNPK(l[2 * p][j], l[2 * p + 1][j], a2[p][j]);
#pragma unroll
    for (int i = 0; i < 8; i++) {
        float b = bconv[kg * 8 + i];
#pragma unroll
        for (int j = 0; j < 4; j++) l[i][j] += b;
    }

    // ---- softmax over K per column ----
#pragma unroll
    for (int j = 0; j < 4; j++) {
        float m = l[0][j];
#pragma unroll
        for (int i = 1; i < 8; i++) m = fmaxf(m, l[i][j]);
        smf[42752 + (sc * 4 + j) * 17 + kg] = m;
    }
    __syncthreads();
    if (tid < 128) {
        float m = smf[42752 + tid * 17];
#pragma unroll
        for (int t = 1; t < 8; t++) m = fmaxf(m, smf[42752 + tid * 17 + t]);
        smf[44928 + tid] = m;
    }
    __syncthreads();
    float e[8][4];
#pragma unroll
    for (int j = 0; j < 4; j++) {
        float M = smf[44928 + sc * 4 + j];
        float ssum = 0.f;
#pragma unroll
        for (int i = 0; i < 8; i++) { e[i][j] = __expf(l[i][j] - M); ssum += e[i][j]; }
        smf[42752 + (sc * 4 + j) * 17 + kg] = ssum;
    }
    __syncthreads();
    if (tid < 128) {
        float t = 0.f;
#pragma unroll
        for (int qq = 0; qq < 8; qq++) t += smf[42752 + tid * 17 + qq];
        smf[44928 + tid] = 1.f / t;
    }
    __syncthreads();

    // ---- saT[s][k] at EP2 (overwrites WconvT) + sasum partials ----
    float ps[8];
#pragma unroll
    for (int i = 0; i < 8; i++) ps[i] = 0.f;
#pragma unroll
    for (int j = 0; j < 4; j++) {
        int sl = sc * 4 + j;
        float r = ((s0 + sl) < 784) ? smf[44928 + sl] : 0.f;
#pragma unroll
        for (int i = 0; i < 8; i++) {
            float val = e[i][j] * r;
            smf[34048 + sl * 68 + kg * 8 + i] = val;
            ps[i] += val;
        }
    }
    __syncthreads();
#pragma unroll
    for (int i = 0; i < 8; i++)
        smf[42752 + (kg * 8 + i) * 34 + sc] = ps[i];
    __syncthreads();
    if (tid < 64) {
        float s = 0.f;
#pragma unroll
        for (int c = 0; c < 32; c++) s += smf[42752 + tid * 34 + c];
        atomicAdd(&g_sasum[n * 64 + tid], s);
    }

    // ---- vlad partial: saT @ xfB -> atomic accumulate into g_vladraw ----
    const int tk = tid >> 4;    // k base tk*4
    const int dg = tid & 15;    // d base dg*8
    unsigned long long vacc[4][4];
#pragma unroll
    for (int qk = 0; qk < 4; qk++)
#pragma unroll
        for (int p = 0; p < 4; p++) vacc[qk][p] = 0ull;
    for (int s = 0; s < 128; s++) {
        float4 sv = *(const float4*)&smf[34048 + s * 68 + tk * 4];
        ulonglong2 xa = *(const ulonglong2*)&smf[17152 + s * 132 + dg * 8];
        ulonglong2 xb = *(const ulonglong2*)&smf[17152 + s * 132 + dg * 8 + 4];
        unsigned long long d0, d1, d2, d3;
        DUP2(d0, sv.x); DUP2(d1, sv.y); DUP2(d2, sv.z); DUP2(d3, sv.w);
        FMA2(vacc[0][0], d0, xa.x); FMA2(vacc[0][1], d0, xa.y);
        FMA2(vacc[0][2], d0, xb.x); FMA2(vacc[0][3], d0, xb.y);
        FMA2(vacc[1][0], d1, xa.x); FMA2(vacc[1][1], d1, xa.y);
        FMA2(vacc[1][2], d1, xb.x); FMA2(vacc[1][3], d1, xb.y);
        FMA2(vacc[2][0], d2, xa.x); FMA2(vacc[2][1], d2, xa.y);
        FMA2(vacc[2][2], d2, xb.x); FMA2(vacc[2][3], d2, xb.y);
        FMA2(vacc[3][0], d3, xa.x); FMA2(vacc[3][1], d3, xa.y);
        FMA2(vacc[3][2], d3, xb.x); FMA2(vacc[3][3], d3, xb.y);
    }
    float* vr = g_vladraw + (size_t)n * 8192;
#pragma unroll
    for (int qk = 0; qk < 4; qk++)
#pragma unroll
        for (int p = 0; p < 4; p++) {
            float lo, hi;
            UNPK(lo, hi, vacc[qk][p]);
            int base = (tk * 4 + qk) * 128 + dg * 8 + p * 2;
            atomicAdd(&vr[base], lo);
            atomicAdd(&vr[base + 1], hi);
        }
}

// ---------------------------------------------------------------------------
// kBfin: vlad = vladraw - centroids*sasum, intra-norm over K. grid 32 x 128thr
// ---------------------------------------------------------------------------
__global__ void __launch_bounds__(128) kBfin(const float* __restrict__ centroids) {
    __shared__ float ssm[64];
    const int n = blockIdx.x, d = threadIdx.x;
    if (d < 64) ssm[d] = g_sasum[n * 64 + d];
    __syncthreads();
    const float* vr = g_vladraw + (size_t)n * 8192;
    float sumsq = 0.f;
#pragma unroll 8
    for (int k = 0; k < 64; k++) {
        float v = vr[k * 128 + d] - centroids[k * 128 + d] * ssm[k];
        sumsq += v * v;
    }
    float inv = 1.f / fmaxf(sqrtf(sumsq), 1e-12f);
    float* vo = g_vlad + (size_t)n * 8192;
#pragma unroll 8
    for (int k = 0; k < 64; k++) {
        float v = vr[k * 128 + d] - centroids[k * 128 + d] * ssm[k];
        vo[k * 128 + d] = v * inv;
    }
}

// ---------------------------------------------------------------------------
// kC: proj += vlad @ Wproj^T.  grid (8 o-tiles of 128, 16 j-splits of 512), 256 thr
// ---------------------------------------------------------------------------
__global__ void __launch_bounds__(256) kC(const float* __restrict__ Wproj) {
    __shared__ float wT[32 * 132];   // [j][o]
    __shared__ float vT[32 * 36];    // [j][n]
    const int tid = threadIdx.x;
    const int ob = blockIdx.x * 128;
    const int jb = blockIdx.y * 512;
    const int og = tid >> 4;       // o base og*8
    const int ng = tid & 15;       // n pair base ng*2

    unsigned long long acc[8];
#pragma unroll
    for (int i = 0; i < 8; i++) acc[i] = 0ull;

    const int wo = tid >> 1, wj = (tid & 1) * 16;
    const int vn = tid >> 3, vj = (tid & 7) * 4;

    for (int jt = 0; jt < 512; jt += 32) {
        __syncthreads();
        {
            const float* wr = &Wproj[(size_t)(ob + wo) * 8192 + jb + jt + wj];
#pragma unroll
            for (int u = 0; u < 4; u++) {
                float4 w = *(const float4*)&wr[u * 4];
                wT[(wj + u * 4 + 0) * 132 + wo] = w.x;
                wT[(wj + u * 4 + 1) * 132 + wo] = w.y;
                wT[(wj + u * 4 + 2) * 132 + wo] = w.z;
                wT[(wj + u * 4 + 3) * 132 + wo] = w.w;
            }
            float4 v = *(const float4*)&g_vlad[(size_t)vn * 8192 + jb + jt + vj];
            vT[(vj + 0) * 36 + vn] = v.x;
            vT[(vj + 1) * 36 + vn] = v.y;
            vT[(vj + 2) * 36 + vn] = v.z;
            vT[(vj + 3) * 36 + vn] = v.w;
        }
        __syncthreads();
#pragma unroll
        for (int j = 0; j < 32; j++) {
            float4 w0 = *(const float4*)&wT[j * 132 + og * 8];
            float4 w1 = *(const float4*)&wT[j * 132 + og * 8 + 4];
            unsigned long long vp = *(const unsigned long long*)&vT[j * 36 + ng * 2];
            unsigned long long wd[8];
            DUP2(wd[0], w0.x); DUP2(wd[1], w0.y); DUP2(wd[2], w0.z); DUP2(wd[3], w0.w);
            DUP2(wd[4], w1.x); DUP2(wd[5], w1.y); DUP2(wd[6], w1.z); DUP2(wd[7], w1.w);
#pragma unroll
            for (int i = 0; i < 8; i++) FMA2(acc[i], wd[i], vp);
        }
    }
#pragma unroll
    for (int i = 0; i < 8; i++) {
        float lo, hi;
        UNPK(lo, hi, acc[i]);
        int o = ob + og * 8 + i;
        atomicAdd(&g_proj[(ng * 2 + 0) * 1024 + o], lo);
        atomicAdd(&g_proj[(ng * 2 + 1) * 1024 + o], hi);
    }
}

// ---------------------------------------------------------------------------
// kD: bias + final L2 norm -> output
// ---------------------------------------------------------------------------
__global__ void __launch_bounds__(256) kD(const float* __restrict__ bproj,
                                          float* __restrict__ out) {
    __shared__ float wr[8];
    __shared__ float inv_s;
    const int n = blockIdx.x, tid = threadIdx.x;
    float v[4]; float ps = 0.f;
#pragma unroll
    for (int r = 0; r < 4; r++) {
        int o = r * 256 + tid;
        v[r] = g_proj[n * 1024 + o] + bproj[o];
        ps += v[r] * v[r];
    }
#pragma unroll
    for (int off = 16; off; off >>= 1)
        ps += __shfl_xor_sync(0xffffffffu, ps, off);
    if ((tid & 31) == 0) wr[tid >> 5] = ps;
    __syncthreads();
    if (tid == 0) {
        float s = 0.f;
#pragma unroll
        for (int t = 0; t < 8; t++) s += wr[t];
        inv_s = 1.f / fmaxf(sqrtf(s), 1e-12f);
    }
    __syncthreads();
#pragma unroll
    for (int r = 0; r < 4; r++)
        out[n * 1024 + r * 256 + tid] = v[r] * inv_s;
}

// ---------------------------------------------------------------------------
extern "C" void kernel_launch(void* const* d_in, const int* in_sizes, int n_in,
                              void* d_out, int out_size) {
    const float* x         = (const float*)d_in[0];
    const float* Wpool     = (const float*)d_in[1];
    const float* bpool     = (const float*)d_in[2];
    const float* Wconv     = (const float*)d_in[3];
    const float* bconv     = (const float*)d_in[4];
    const float* centroids = (const float*)d_in[5];
    const float* Wproj     = (const float*)d_in[6];
    const float* bproj     = (const float*)d_in[7];
    float* out = (float*)d_out;

    cudaFuncSetAttribute(kA, cudaFuncAttributeMaxDynamicSharedMemorySize, 180224);

    kW<<<512, 256>>>(Wpool);
    kZ<<<1024, 256>>>();
    dim3 gA(7, 32);
    kA<<<gA, 256, 180224>>>(x, bpool, Wconv, bconv);
    kBfin<<<32, 128>>>(centroids);
    dim3 gC(8, 16);
    kC<<<gC, 256>>>(Wproj);
    kD<<<32, 256>>>(bproj, out);
}

// round 8
// speedup vs baseline: 1.9180x; 1.0301x over previous
#include <cuda_runtime.h>
#include <cuda_bf16.h>
#include <cstdint>

// ---------------------------------------------------------------------------
// NetVLAD GB300 round 6: HMMA bf16-split pool GEMM, s-tile 64, 2 blocks/SM
// N=32, C=1024, D=128, K=64, S=784 (13 tiles of 64), OUT=1024
// ---------------------------------------------------------------------------

__device__ __nv_bfloat16 g_wh[131072];    // Wpool hi [d][c]
__device__ __nv_bfloat16 g_wl[131072];    // Wpool lo [d][c]
__device__ float g_vladraw[32 * 8192];
__device__ float g_vlad  [32 * 8192];
__device__ float g_sasum [32 * 64];
__device__ float g_proj  [32 * 1024];

#define FMA2(acc, a, b) \
    asm("fma.rn.f32x2 %0, %1, %2, %0;" : "+l"(acc) : "l"(a), "l"(b))
#define DUP2(d, s) \
    asm("mov.b64 %0, {%1, %1};" : "=l"(d) : "f"(s))
#define UNPK(lo, hi, s) \
    asm("mov.b64 {%0, %1}, %2;" : "=f"(lo), "=f"(hi) : "l"(s))

__device__ __forceinline__ uint32_t smem_u32(const void* p) {
    uint32_t a;
    asm("{ .reg .u64 t; cvta.to.shared.u64 t, %1; cvt.u32.u64 %0, t; }"
        : "=r"(a) : "l"(p));
    return a;
}
__device__ __forceinline__ void ldsm(unsigned* r, uint32_t a) {
    asm volatile("ldmatrix.sync.aligned.m8n8.x4.shared.b16 {%0,%1,%2,%3}, [%4];"
        : "=r"(r[0]), "=r"(r[1]), "=r"(r[2]), "=r"(r[3]) : "r"(a));
}
__device__ __forceinline__ void ldsmt(unsigned* r, uint32_t a) {
    asm volatile("ldmatrix.sync.aligned.m8n8.x4.trans.shared.b16 {%0,%1,%2,%3}, [%4];"
        : "=r"(r[0]), "=r"(r[1]), "=r"(r[2]), "=r"(r[3]) : "r"(a));
}
__device__ __forceinline__ void mma_bf16(float* c, const unsigned* a, const unsigned* b) {
    asm volatile(
        "mma.sync.aligned.m16n8k16.row.col.f32.bf16.bf16.f32 "
        "{%0,%1,%2,%3}, {%4,%5,%6,%7}, {%8,%9}, {%0,%1,%2,%3};"
        : "+f"(c[0]), "+f"(c[1]), "+f"(c[2]), "+f"(c[3])
        : "r"(a[0]), "r"(a[1]), "r"(a[2]), "r"(a[3]), "r"(b[0]), "r"(b[1]));
}
static __device__ __forceinline__ uint32_t packbf2(float a, float b) {
    __nv_bfloat162 t;
    t.x = __float2bfloat16(a);
    t.y = __float2bfloat16(b);
    return *(uint32_t*)&t;
}

// ---------------------------------------------------------------------------
__global__ void kW(const float* __restrict__ Wpool) {
    int idx = blockIdx.x * 256 + threadIdx.x;
    if (idx >= 131072) return;
    float w = Wpool[idx];
    __nv_bfloat16 h = __float2bfloat16(w);
    g_wh[idx] = h;
    g_wl[idx] = __float2bfloat16(w - __bfloat162float(h));
}

__global__ void kZ() {
    int idx = blockIdx.x * 256 + threadIdx.x;
    if (idx < 262144) g_vladraw[idx] = 0.f;
    if (idx < 2048)   g_sasum[idx] = 0.f;
    if (idx < 32768)  g_proj[idx] = 0.f;
}

// ---------------------------------------------------------------------------
// kA: HMMA pool GEMM (128d x 64s) + bias + col L2 norm + logits + softmax
//     + fused vlad partial.  grid (13 s-tiles, 32 n), 256 thr, smem 78592 B
// phase1 bytes: WH@1024 [128][72bf16] 18432 | WL@19456 | XH@37888 [64][72bf16]
//   9216 | XL@47104 9216
// phase2 floats: XF_A@256 [128][68] (acc -> WconvT -> saT)
//   XF_B@8960 [64 s][132 d] | EP3@17408 [64][34] | EP4@19584 [64]
// ---------------------------------------------------------------------------
__global__ void __launch_bounds__(256, 2) kA(const float* __restrict__ x,
                                             const float* __restrict__ bpool,
                                             const float* __restrict__ Wconv,
                                             const float* __restrict__ bconv) {
    extern __shared__ char smc[];
    float* smf = (float*)smc;
    const uint32_t sb = smem_u32(smc);

    const int tid = threadIdx.x, lane = tid & 31, wid = tid >> 5;
    const int n = blockIdx.y;
    const int s0 = blockIdx.x * 64;
    const bool fullv = (blockIdx.x < 12);

    const int WHo = 1024, WLo = 19456, XHo = 37888, XLo = 47104;
    const int XF_A = 256, XF_B = 8960, EP3 = 17408, EP4 = 19584;

    const float* xn = x + (size_t)n * 1024 * 784;
    const int xc = tid >> 2, xs = (tid & 3) * 16;     // X staging: c row, s sub
    const int wrow = tid >> 1, wcol = (tid & 1) * 32; // W staging

    const int wd = wid & 3, ws = wid >> 2;
    const int md0 = wd * 32, ns0 = ws * 32;
    const int mat = lane >> 3, rr = lane & 7;
    const uint32_t aH = sb + WHo + (uint32_t)(md0 + ((mat & 1) << 3) + rr) * 144
                        + ((uint32_t)(mat >> 1) << 4);
    const uint32_t aL = aH + 18432;
    const uint32_t bHb = sb + XHo + (uint32_t)(((mat & 1) << 3) + rr) * 144
                         + (uint32_t)(ns0 + ((mat >> 1) << 3)) * 2;
    const uint32_t bLb = bHb + 9216;

    float acc[2][4][4];
#pragma unroll
    for (int mt = 0; mt < 2; mt++)
#pragma unroll
        for (int nf = 0; nf < 4; nf++)
#pragma unroll
            for (int u = 0; u < 4; u++) acc[mt][nf][u] = 0.f;

    for (int q = 0; q < 16; q++) {
        if (q) __syncthreads();
        // ---- W chunk: 32 bf16 per plane per thread ----
        {
            const uint4* ph = (const uint4*)(g_wh + (size_t)wrow * 1024 + q * 64 + wcol);
            const uint4* pl = (const uint4*)(g_wl + (size_t)wrow * 1024 + q * 64 + wcol);
            uint4 h[4], l4[4];
#pragma unroll
            for (int u = 0; u < 4; u++) { h[u] = ph[u]; l4[u] = pl[u]; }
            char* dh = smc + WHo + wrow * 144 + wcol * 2;
            char* dl = smc + WLo + wrow * 144 + wcol * 2;
#pragma unroll
            for (int u = 0; u < 4; u++) {
                ((uint4*)dh)[u] = h[u];
                ((uint4*)dl)[u] = l4[u];
            }
        }
        // ---- X chunk: one c-row x 16 s, convert to hi/lo bf16 ----
        {
            const float* p0 = xn + (size_t)(q * 64 + xc) * 784 + s0 + xs;
            float t[16];
            if (fullv) {
#pragma unroll
                for (int u = 0; u < 4; u++) {
                    float4 a = ((const float4*)p0)[u];
                    t[u * 4] = a.x; t[u * 4 + 1] = a.y;
                    t[u * 4 + 2] = a.z; t[u * 4 + 3] = a.w;
                }
            } else {
#pragma unroll
                for (int i = 0; i < 16; i++)
                    t[i] = ((s0 + xs + i) < 784) ? p0[i] : 0.f;
            }
            char* xh = smc + XHo + xc * 144 + xs * 2;
            char* xl = smc + XLo + xc * 144 + xs * 2;
#pragma unroll
            for (int i = 0; i < 8; i++) {
                float v0 = t[2 * i], v1 = t[2 * i + 1];
                __nv_bfloat16 h0 = __float2bfloat16(v0);
                __nv_bfloat16 h1 = __float2bfloat16(v1);
                uint32_t hp;
                { __nv_bfloat162 tt; tt.x = h0; tt.y = h1; hp = *(uint32_t*)&tt; }
                *(uint32_t*)(xh + i * 4) = hp;
                *(uint32_t*)(xl + i * 4) =
                    packbf2(v0 - __bfloat162float(h0), v1 - __bfloat162float(h1));
            }
        }
        __syncthreads();
        // ---- mma: k = 64 in 4 k-steps ----
#pragma unroll
        for (int ks = 0; ks < 4; ks++) {
            unsigned ah[2][4], al[2][4];
            ldsm(ah[0], aH + ks * 32);
            ldsm(ah[1], aH + ks * 32 + 2304);
            ldsm(al[0], aL + ks * 32);
            ldsm(al[1], aL + ks * 32 + 2304);
            unsigned bh[2][4], bl[2][4];
#pragma unroll
            for (int nt = 0; nt < 2; nt++) {
                ldsmt(bh[nt], bHb + ks * 2304 + nt * 32);
                ldsmt(bl[nt], bLb + ks * 2304 + nt * 32);
            }
#pragma unroll
            for (int mt = 0; mt < 2; mt++)
#pragma unroll
                for (int nf = 0; nf < 4; nf++) {
                    const unsigned* bhf = &bh[nf >> 1][(nf & 1) * 2];
                    const unsigned* blf = &bl[nf >> 1][(nf & 1) * 2];
                    mma_bf16(acc[mt][nf], ah[mt], bhf);
                    mma_bf16(acc[mt][nf], al[mt], bhf);
                    mma_bf16(acc[mt][nf], ah[mt], blf);
                }
        }
    }
    __syncthreads();

    // ---- acc -> XF_A[d][s] (+bias) ----
    {
        const int r0w = lane >> 2, cq = (lane & 3) * 2;
#pragma unroll
        for (int mt = 0; mt < 2; mt++) {
            int d = md0 + mt * 16 + r0w;
            float b0 = __ldg(&bpool[d]);
            float b8 = __ldg(&bpool[d + 8]);
#pragma unroll
            for (int nf = 0; nf < 4; nf++) {
                int s = ns0 + nf * 8 + cq;
                smf[XF_A + d * 68 + s]           = acc[mt][nf][0] + b0;
                smf[XF_A + d * 68 + s + 1]       = acc[mt][nf][1] + b0;
                smf[XF_A + (d + 8) * 68 + s]     = acc[mt][nf][2] + b8;
                smf[XF_A + (d + 8) * 68 + s + 1] = acc[mt][nf][3] + b8;
            }
        }
    }
    __syncthreads();

    // ---- column L2 norm over d ----
    if (tid < 64) {
        float s = 0.f;
#pragma unroll 8
        for (int d = 0; d < 128; d++) {
            float v = smf[XF_A + d * 68 + tid];
            s += v * v;
        }
        smf[EP4 + tid] = ((s0 + tid) < 784) ? 1.f / fmaxf(sqrtf(s), 1e-12f) : 0.f;
    }
    __syncthreads();

    // ---- build normalized XF_B[s][d] ----
    {
        const int row = tid & 127, hs = tid >> 7;
#pragma unroll
        for (int g = 0; g < 8; g++) {
            int s4 = hs * 32 + g * 4;
            float4 v = *(const float4*)&smf[XF_A + row * 68 + s4];
            float4 m = *(const float4*)&smf[EP4 + s4];
            smf[XF_B + (s4 + 0) * 132 + row] = v.x * m.x;
            smf[XF_B + (s4 + 1) * 132 + row] = v.y * m.y;
            smf[XF_B + (s4 + 2) * 132 + row] = v.z * m.z;
            smf[XF_B + (s4 + 3) * 132 + row] = v.w * m.w;
        }
    }
    __syncthreads();

    // ---- stage WconvT[d][k] into XF_A region ----
    {
        int kr = tid & 63, dq = tid >> 6;
#pragma unroll
        for (int u = 0; u < 8; u++) {
            float4 w = *(const float4*)&Wconv[kr * 128 + dq * 32 + u * 4];
            smf[XF_A + (dq * 32 + u * 4 + 0) * 68 + kr] = w.x;
            smf[XF_A + (dq * 32 + u * 4 + 1) * 68 + kr] = w.y;
            smf[XF_A + (dq * 32 + u * 4 + 2) * 68 + kr] = w.z;
            smf[XF_A + (dq * 32 + u * 4 + 3) * 68 + kr] = w.w;
        }
    }
    __syncthreads();

    // ---- logits: kg -> 8 k, sc -> s pair {2sc, 2sc+1} ----
    const int kg = tid & 7;
    const int sc = tid >> 3;
    unsigned long long a2[4][2];
#pragma unroll
    for (int p = 0; p < 4; p++) { a2[p][0] = 0ull; a2[p][1] = 0ull; }
    for (int d = 0; d < 128; d++) {
        ulonglong2 w0 = *(const ulonglong2*)&smf[XF_A + d * 68 + kg * 8];
        ulonglong2 w1 = *(const ulonglong2*)&smf[XF_A + d * 68 + kg * 8 + 4];
        float x0 = smf[XF_B + (2 * sc) * 132 + d];
        float x1 = smf[XF_B + (2 * sc + 1) * 132 + d];
        unsigned long long xd0, xd1;
        DUP2(xd0, x0); DUP2(xd1, x1);
        FMA2(a2[0][0], w0.x, xd0); FMA2(a2[0][1], w0.x, xd1);
        FMA2(a2[1][0], w0.y, xd0); FMA2(a2[1][1], w0.y, xd1);
        FMA2(a2[2][0], w1.x, xd0); FMA2(a2[2][1], w1.x, xd1);
        FMA2(a2[3][0], w1.y, xd0); FMA2(a2[3][1], w1.y, xd1);
    }
    float l[8][2];
#pragma unroll
    for (int p = 0; p < 4; p++) {
        UNPK(l[2 * p][0], l[2 * p + 1][0], a2[p][0]);
        UNPK(l[2 * p][1], l[2 * p + 1][1], a2[p][1]);
    }
#pragma unroll
    for (int i = 0; i < 8; i++) {
        float b = bconv[kg * 8 + i];
        l[i][0] += b; l[i][1] += b;
    }

    // ---- softmax over K per column ----
#pragma unroll
    for (int j = 0; j < 2; j++) {
        float m = l[0][j];
#pragma unroll
        for (int i = 1; i < 8; i++) m = fmaxf(m, l[i][j]);
        smf[EP3 + (2 * sc + j) * 17 + kg] = m;
    }
    __syncthreads();
    if (tid < 64) {
        float m = smf[EP3 + tid * 17];
#pragma unroll
        for (int t = 1; t < 8; t++) m = fmaxf(m, smf[EP3 + tid * 17 + t]);
        smf[EP4 + tid] = m;
    }
    __syncthreads();
    float e[8][2];
#pragma unroll
    for (int j = 0; j < 2; j++) {
        float M = smf[EP4 + 2 * sc + j];
        float ssum = 0.f;
#pragma unroll
        for (int i = 0; i < 8; i++) { e[i][j] = __expf(l[i][j] - M); ssum += e[i][j]; }
        smf[EP3 + (2 * sc + j) * 17 + kg] = ssum;
    }
    __syncthreads();
    if (tid < 64) {
        float t = 0.f;
#pragma unroll
        for (int qq = 0; qq < 8; qq++) t += smf[EP3 + tid * 17 + qq];
        smf[EP4 + tid] = 1.f / t;
    }
    __syncthreads();

    // ---- saT[s][k] into XF_A (WconvT dead) + sasum partials ----
    float ps[8];
#pragma unroll
    for (int i = 0; i < 8; i++) ps[i] = 0.f;
#pragma unroll
    for (int j = 0; j < 2; j++) {
        int sl = 2 * sc + j;
        float r = ((s0 + sl) < 784) ? smf[EP4 + sl] : 0.f;
#pragma unroll
        for (int i = 0; i < 8; i++) {
            float val = e[i][j] * r;
            smf[XF_A + sl * 68 + kg * 8 + i] = val;
            ps[i] += val;
        }
    }
    __syncthreads();
#pragma unroll
    for (int i = 0; i < 8; i++)
        smf[EP3 + (kg * 8 + i) * 34 + sc] = ps[i];
    __syncthreads();
    if (tid < 64) {
        float s = 0.f;
#pragma unroll
        for (int c = 0; c < 32; c++) s += smf[EP3 + tid * 34 + c];
        atomicAdd(&g_sasum[n * 64 + tid], s);
    }

    // ---- vlad partial: saT @ XF_B -> g_vladraw ----
    const int tk = tid >> 4;    // k base tk*4
    const int dg = tid & 15;    // d base dg*8
    unsigned long long vacc[4][4];
#pragma unroll
    for (int qk = 0; qk < 4; qk++)
#pragma unroll
        for (int p = 0; p < 4; p++) vacc[qk][p] = 0ull;
    for (int s = 0; s < 64; s++) {
        float4 sv = *(const float4*)&smf[XF_A + s * 68 + tk * 4];
        ulonglong2 xa = *(const ulonglong2*)&smf[XF_B + s * 132 + dg * 8];
        ulonglong2 xb = *(const ulonglong2*)&smf[XF_B + s * 132 + dg * 8 + 4];
        unsigned long long d0, d1, d2, d3;
        DUP2(d0, sv.x); DUP2(d1, sv.y); DUP2(d2, sv.z); DUP2(d3, sv.w);
        FMA2(vacc[0][0], d0, xa.x); FMA2(vacc[0][1], d0, xa.y);
        FMA2(vacc[0][2], d0, xb.x); FMA2(vacc[0][3], d0, xb.y);
        FMA2(vacc[1][0], d1, xa.x); FMA2(vacc[1][1], d1, xa.y);
        FMA2(vacc[1][2], d1, xb.x); FMA2(vacc[1][3], d1, xb.y);
        FMA2(vacc[2][0], d2, xa.x); FMA2(vacc[2][1], d2, xa.y);
        FMA2(vacc[2][2], d2, xb.x); FMA2(vacc[2][3], d2, xb.y);
        FMA2(vacc[3][0], d3, xa.x); FMA2(vacc[3][1], d3, xa.y);
        FMA2(vacc[3][2], d3, xb.x); FMA2(vacc[3][3], d3, xb.y);
    }
    float* vr = g_vladraw + (size_t)n * 8192;
#pragma unroll
    for (int qk = 0; qk < 4; qk++)
#pragma unroll
        for (int p = 0; p < 4; p++) {
            float lo, hi;
            UNPK(lo, hi, vacc[qk][p]);
            int base = (tk * 4 + qk) * 128 + dg * 8 + p * 2;
            atomicAdd(&vr[base], lo);
            atomicAdd(&vr[base + 1], hi);
        }
}

// ---------------------------------------------------------------------------
// kBfin: vlad = vladraw - centroids*sasum, intra-norm over K
// grid 32, 256 threads (2 k-halves x 128 d), single pass
// ---------------------------------------------------------------------------
__global__ void __launch_bounds__(256) kBfin(const float* __restrict__ centroids) {
    __shared__ float ssm[64];
    __shared__ float red[2][128];
    const int n = blockIdx.x, tid = threadIdx.x;
    const int kh = tid >> 7, d = tid & 127;
    if (tid < 64) ssm[tid] = g_sasum[n * 64 + tid];
    __syncthreads();
    const float* vr = g_vladraw + (size_t)n * 8192;
    float v[32], sq = 0.f;
#pragma unroll
    for (int j = 0; j < 32; j++) {
        int k = kh * 32 + j;
        float val = vr[k * 128 + d] - centroids[k * 128 + d] * ssm[k];
        v[j] = val;
        sq += val * val;
    }
    red[kh][d] = sq;
    __syncthreads();
    float inv = 1.f / fmaxf(sqrtf(red[0][d] + red[1][d]), 1e-12f);
    float* vo = g_vlad + (size_t)n * 8192;
#pragma unroll
    for (int j = 0; j < 32; j++)
        vo[(kh * 32 + j) * 128 + d] = v[j] * inv;
}

// ---------------------------------------------------------------------------
// kC: proj += vlad @ Wproj^T.  grid (8 o-tiles of 128, 16 j-splits of 512)
// ---------------------------------------------------------------------------
__global__ void __launch_bounds__(256) kC(const float* __restrict__ Wproj) {
    __shared__ float wT[32 * 132];   // [j][o]
    __shared__ float vT[32 * 36];    // [j][n]
    const int tid = threadIdx.x;
    const int ob = blockIdx.x * 128;
    const int jb = blockIdx.y * 512;
    const int og = tid >> 4;
    const int ng = tid & 15;

    unsigned long long acc[8];
#pragma unroll
    for (int i = 0; i < 8; i++) acc[i] = 0ull;

    const int wo = tid >> 1, wj = (tid & 1) * 16;
    const int vn = tid >> 3, vj = (tid & 7) * 4;

    for (int jt = 0; jt < 512; jt += 32) {
        __syncthreads();
        {
            const float* wr = &Wproj[(size_t)(ob + wo) * 8192 + jb + jt + wj];
#pragma unroll
            for (int u = 0; u < 4; u++) {
                float4 w = *(const float4*)&wr[u * 4];
                wT[(wj + u * 4 + 0) * 132 + wo] = w.x;
                wT[(wj + u * 4 + 1) * 132 + wo] = w.y;
                wT[(wj + u * 4 + 2) * 132 + wo] = w.z;
                wT[(wj + u * 4 + 3) * 132 + wo] = w.w;
            }
            float4 v = *(const float4*)&g_vlad[(size_t)vn * 8192 + jb + jt + vj];
            vT[(vj + 0) * 36 + vn] = v.x;
            vT[(vj + 1) * 36 + vn] = v.y;
            vT[(vj + 2) * 36 + vn] = v.z;
            vT[(vj + 3) * 36 + vn] = v.w;
        }
        __syncthreads();
#pragma unroll
        for (int j = 0; j < 32; j++) {
            float4 w0 = *(const float4*)&wT[j * 132 + og * 8];
            float4 w1 = *(const float4*)&wT[j * 132 + og * 8 + 4];
            unsigned long long vp = *(const unsigned long long*)&vT[j * 36 + ng * 2];
            unsigned long long wdr[8];
            DUP2(wdr[0], w0.x); DUP2(wdr[1], w0.y); DUP2(wdr[2], w0.z); DUP2(wdr[3], w0.w);
            DUP2(wdr[4], w1.x); DUP2(wdr[5], w1.y); DUP2(wdr[6], w1.z); DUP2(wdr[7], w1.w);
#pragma unroll
            for (int i = 0; i < 8; i++) FMA2(acc[i], wdr[i], vp);
        }
    }
#pragma unroll
    for (int i = 0; i < 8; i++) {
        float lo, hi;
        UNPK(lo, hi, acc[i]);
        int o = ob + og * 8 + i;
        atomicAdd(&g_proj[(ng * 2 + 0) * 1024 + o], lo);
        atomicAdd(&g_proj[(ng * 2 + 1) * 1024 + o], hi);
    }
}

// ---------------------------------------------------------------------------
__global__ void __launch_bounds__(256) kD(const float* __restrict__ bproj,
                                          float* __restrict__ out) {
    __shared__ float wr[8];
    __shared__ float inv_s;
    const int n = blockIdx.x, tid = threadIdx.x;
    float v[4]; float ps = 0.f;
#pragma unroll
    for (int r = 0; r < 4; r++) {
        int o = r * 256 + tid;
        v[r] = g_proj[n * 1024 + o] + bproj[o];
        ps += v[r] * v[r];
    }
#pragma unroll
    for (int off = 16; off; off >>= 1)
        ps += __shfl_xor_sync(0xffffffffu, ps, off);
    if ((tid & 31) == 0) wr[tid >> 5] = ps;
    __syncthreads();
    if (tid == 0) {
        float s = 0.f;
#pragma unroll
        for (int t = 0; t < 8; t++) s += wr[t];
        inv_s = 1.f / fmaxf(sqrtf(s), 1e-12f);
    }
    __syncthreads();
#pragma unroll
    for (int r = 0; r < 4; r++)
        out[n * 1024 + r * 256 + tid] = v[r] * inv_s;
}

// ---------------------------------------------------------------------------
extern "C" void kernel_launch(void* const* d_in, const int* in_sizes, int n_in,
                              void* d_out, int out_size) {
    const float* x         = (const float*)d_in[0];
    const float* Wpool     = (const float*)d_in[1];
    const float* bpool     = (const float*)d_in[2];
    const float* Wconv     = (const float*)d_in[3];
    const float* bconv     = (const float*)d_in[4];
    const float* centroids = (const float*)d_in[5];
    const float* Wproj     = (const float*)d_in[6];
    const float* bproj     = (const float*)d_in[7];
    float* out = (float*)d_out;

    cudaFuncSetAttribute(kA, cudaFuncAttributeMaxDynamicSharedMemorySize, 78592);

    kW<<<512, 256>>>(Wpool);
    kZ<<<1024, 256>>>();
    dim3 gA(13, 32);
    kA<<<gA, 256, 78592>>>(x, bpool, Wconv, bconv);
    kBfin<<<32, 256>>>(centroids);
    dim3 gC(8, 16);
    kC<<<gC, 256>>>(Wproj);
    kD<<<32, 256>>>(bproj, out);
}